// round 12
// baseline (speedup 1.0000x reference)
#include <cuda_runtime.h>
#include <cuda_fp16.h>
#include <mma.h>
#include <math.h>

// Problem constants
#define B      256
#define NNEG   1000
#define H      3
#define D      128
#define CMAX   250          // neg indices < min(NUM_CLUSTER) = 250
#define CPAD   256          // padded cluster dim
#define EPSF   1e-6f
#define NPROD  48           // 4 c-tiles x 4 b-tiles x 3 h
#define NGRP   4            // b-groups of 64
#define PROD_PER_GRP 12     // 4 c-tiles x 3 h

using namespace nvcuda;

// Device globals (no allocation allowed)
__device__ float g_S[B * H * CPAD];       // sim matrix (dot+1)/2, [b][h][c]
__device__ float g_loss[B];               // per-sample loss
__device__ int   g_cntP[NGRP];            // producer arrivals per group
__device__ int   g_cntC[NGRP];            // consumer completions per group
__device__ unsigned int g_done = 0;       // global completion counter

union SMem {
    struct {                               // producer view (33 KB)
        __half A[64 * 128];                // se tile fp16 (16 KB); reused as C fp32
        __half Bt[64 * 128];               // centroid tile fp16 (16 KB)
        float  invSe[64];
        float  invC[64];
    } p;
    struct {                               // consumer view (~3.1 KB)
        float sS[H * CPAD];
        float sPos[H];
        int   sLab[H];
        float rL[8];
        float rC[8];
        int   sLast;
    } c;
};

__global__ void __launch_bounds__(256, 4)
hirl(const float* __restrict__ se,
     const float* __restrict__ c0,
     const float* __restrict__ c1,
     const float* __restrict__ c2,
     const int* __restrict__ i2c0,
     const int* __restrict__ i2c1,
     const int* __restrict__ i2c2,
     const int* __restrict__ index,
     const int* __restrict__ neg,
     float* __restrict__ out) {
    __shared__ __align__(32) SMem sm;

    const int tid  = threadIdx.x;
    const int w    = tid >> 5;
    const int lane = tid & 31;
    const int bid  = blockIdx.x;

    if (bid < NPROD) {
        // ============ PRODUCER: 64b x 64c wmma sim tile ============
        const int x = bid & 3;               // c-tile
        const int y = (bid >> 2) & 3;        // b-group (64 b's)
        const int h = bid >> 4;              // 0..2
        const int cbase = x * 64;
        const int b0 = y * 64;
        const float* cents = (h == 0) ? c0 : (h == 1) ? c1 : c2;

        // Load + convert se rows: warp w handles rows w*8 .. w*8+7.
        #pragma unroll
        for (int rr = 0; rr < 8; rr++) {
            int row = w * 8 + rr;
            float4 v = ((const float4*)(se + ((size_t)(b0 + row) * H + h) * D))[lane];
            float ss = v.x * v.x + v.y * v.y + v.z * v.z + v.w * v.w;
            #pragma unroll
            for (int o = 16; o > 0; o >>= 1) ss += __shfl_xor_sync(0xffffffffu, ss, o);
            if (lane == 0) sm.p.invSe[row] = 1.0f / fmaxf(sqrtf(ss), 1e-12f);
            __half2* dst = (__half2*)(sm.p.A + row * 128 + lane * 4);
            dst[0] = __floats2half2_rn(v.x, v.y);
            dst[1] = __floats2half2_rn(v.z, v.w);
        }
        // Load + convert centroid rows.
        #pragma unroll
        for (int rr = 0; rr < 8; rr++) {
            int row = w * 8 + rr;
            int c = cbase + row;
            float4 v = make_float4(0.f, 0.f, 0.f, 0.f);
            if (c < CMAX) v = ((const float4*)(cents + (size_t)c * D))[lane];
            float ss = v.x * v.x + v.y * v.y + v.z * v.z + v.w * v.w;
            #pragma unroll
            for (int o = 16; o > 0; o >>= 1) ss += __shfl_xor_sync(0xffffffffu, ss, o);
            if (lane == 0)
                sm.p.invC[row] = (c < CMAX) ? 1.0f / fmaxf(sqrtf(ss), 1e-12f) : 0.0f;
            __half2* dst = (__half2*)(sm.p.Bt + row * 128 + lane * 4);
            dst[0] = __floats2half2_rn(v.x, v.y);
            dst[1] = __floats2half2_rn(v.z, v.w);
        }
        __syncthreads();

        // wmma: warp w -> b-subtile (w>>1), c-subtiles (w&1)*2 + {0,1}.
        const int btl = w >> 1;
        const int ctp = (w & 1) * 2;
        wmma::fragment<wmma::accumulator, 16, 16, 16, float> fc0, fc1;
        wmma::fill_fragment(fc0, 0.0f);
        wmma::fill_fragment(fc1, 0.0f);
        {
            wmma::fragment<wmma::matrix_a, 16, 16, 16, __half, wmma::row_major> fa;
            wmma::fragment<wmma::matrix_b, 16, 16, 16, __half, wmma::col_major> fb;
            #pragma unroll
            for (int k = 0; k < 8; k++) {
                wmma::load_matrix_sync(fa, sm.p.A + (btl * 16) * 128 + k * 16, 128);
                wmma::load_matrix_sync(fb, sm.p.Bt + (ctp * 16) * 128 + k * 16, 128);
                wmma::mma_sync(fc0, fa, fb, fc0);
                wmma::load_matrix_sync(fb, sm.p.Bt + ((ctp + 1) * 16) * 128 + k * 16, 128);
                wmma::mma_sync(fc1, fa, fb, fc1);
            }
        }
        __syncthreads();                 // done reading A/Bt

        float* C_s = (float*)sm.p.A;     // reuse A as fp32 C tile (16 KB)
        wmma::store_matrix_sync(C_s + (btl * 16) * 64 + ctp * 16, fc0, 64,
                                wmma::mem_row_major);
        wmma::store_matrix_sync(C_s + (btl * 16) * 64 + (ctp + 1) * 16, fc1, 64,
                                wmma::mem_row_major);
        __syncthreads();

        // Scale + write g_S: 1024 float4 chunks, 4 per thread.
        #pragma unroll
        for (int k = 0; k < 4; k++) {
            int i = tid + k * 256;
            int bi = i >> 4;
            int ci = (i & 15) * 4;
            float4 v = ((const float4*)C_s)[i];
            float is = sm.p.invSe[bi];
            v.x = (v.x * is * sm.p.invC[ci + 0] + 1.0f) * 0.5f;
            v.y = (v.y * is * sm.p.invC[ci + 1] + 1.0f) * 0.5f;
            v.z = (v.z * is * sm.p.invC[ci + 2] + 1.0f) * 0.5f;
            v.w = (v.w * is * sm.p.invC[ci + 3] + 1.0f) * 0.5f;
            *((float4*)(g_S + ((size_t)(b0 + bi) * H + h) * CPAD + cbase + ci)) = v;
        }
        __syncthreads();
        if (tid == 0) {
            __threadfence();             // release g_S stores
            atomicAdd(&g_cntP[y], 1);
        }
        return;
    }

    // ============ CONSUMER: loss for one b ============
    const int b = bid - NPROD;
    const int grp = b >> 6;

    // ---- pre-wait #1: neg triples into registers (4 per thread) ----
    int4 na, nb, nc;
    const bool on = (tid < 250);
    if (on) {
        const int4* p = ((const int4*)(neg + (size_t)b * NNEG * H)) + tid * 3;
        na = p[0]; nb = p[1]; nc = p[2];
    }

    // ---- pre-wait #2: pos path (warps 0-2, h = w) ----
    if (w < H) {
        int idx = index[b];
        const int*   i2c   = (w == 0) ? i2c0 : (w == 1) ? i2c1 : i2c2;
        const float* cents = (w == 0) ? c0   : (w == 1) ? c1   : c2;
        int lab = i2c[idx];
        float4 cv = ((const float4*)(cents + (size_t)lab * D))[lane];
        float4 sv = ((const float4*)(se + ((size_t)b * H + w) * D))[lane];
        float cc = cv.x * cv.x + cv.y * cv.y + cv.z * cv.z + cv.w * cv.w;
        float ee = sv.x * sv.x + sv.y * sv.y + sv.z * sv.z + sv.w * sv.w;
        float dd = cv.x * sv.x + cv.y * sv.y + cv.z * sv.z + cv.w * sv.w;
        #pragma unroll
        for (int o = 16; o > 0; o >>= 1) {
            cc += __shfl_xor_sync(0xffffffffu, cc, o);
            ee += __shfl_xor_sync(0xffffffffu, ee, o);
            dd += __shfl_xor_sync(0xffffffffu, dd, o);
        }
        if (lane == 0) {
            float s = dd / (fmaxf(sqrtf(cc), 1e-12f) * fmaxf(sqrtf(ee), 1e-12f));
            sm.c.sPos[w] = (s + 1.0f) * 0.5f;
            sm.c.sLab[w] = lab;
        }
    }

    // ---- wait for this group's 12 producers ----
    if (tid == 0) {
        while (atomicAdd(&g_cntP[grp], 0) < PROD_PER_GRP) __nanosleep(64);
        __threadfence();                 // acquire
    }
    __syncthreads();

    // ---- stage S row (3 KB) ----
    if (tid < 192)
        ((float4*)sm.c.sS)[tid] = ((const float4*)(g_S + (size_t)b * H * CPAD))[tid];
    __syncthreads();

    // ---- loss: 4 negs/thread, ONE log per thread (merged product) ----
    const int lab0 = sm.c.sLab[0], lab1 = sm.c.sLab[1], lab2 = sm.c.sLab[2];
    float prodv = 1.0f, cnt = 0.0f;
    if (on) {
        int idx0[4] = { na.x, na.w, nb.z, nc.y };
        int idx1[4] = { na.y, nb.x, nb.w, nc.z };
        int idx2[4] = { na.z, nb.y, nc.x, nc.w };
        #pragma unroll
        for (int k = 0; k < 4; k++) {
            int i0 = idx0[k], i1 = idx1[k], i2 = idx2[k];
            float p = sm.c.sS[i0] * sm.c.sS[CPAD + i1] * sm.c.sS[2 * CPAD + i2];
            bool tn = (i0 != lab0) || (i1 != lab1) || (i2 != lab2);
            if (tn) {
                prodv *= (1.0f - p + EPSF);
                cnt   += 1.0f;
            }
        }
    }
    float sumL = -__logf(prodv);
    #pragma unroll
    for (int o = 16; o > 0; o >>= 1) {
        sumL += __shfl_xor_sync(0xffffffffu, sumL, o);
        cnt  += __shfl_xor_sync(0xffffffffu, cnt,  o);
    }
    if (lane == 0) { sm.c.rL[w] = sumL; sm.c.rC[w] = cnt; }
    __syncthreads();

    if (tid == 0) {
        float sL = 0.0f, sC = 0.0f;
        #pragma unroll
        for (int i = 0; i < 8; i++) { sL += sm.c.rL[i]; sC += sm.c.rC[i]; }
        float negl = sL / (sC + EPSF);
        float posl = -__logf(sm.c.sPos[0] * sm.c.sPos[1] * sm.c.sPos[2] + EPSF);
        g_loss[b] = 0.5f * (posl + negl);
        __threadfence();
        // group bookkeeping: 64th consumer resets this group's counters
        int cc2 = atomicAdd(&g_cntC[grp], 1);
        if (cc2 == 63) {
            g_cntP[grp] = 0;
            g_cntC[grp] = 0;
        }
        unsigned int t = atomicAdd(&g_done, 1u);
        sm.c.sLast = (t == (unsigned)(B - 1)) ? 1 : 0;
    }
    __syncthreads();

    // ---- last consumer: deterministic final mean ----
    if (sm.c.sLast) {
        __threadfence();
        float v = *((volatile float*)&g_loss[tid]);   // tid 0..255 == b
        #pragma unroll
        for (int o = 16; o > 0; o >>= 1) v += __shfl_xor_sync(0xffffffffu, v, o);
        if (lane == 0) sm.c.rL[w] = v;
        __syncthreads();
        if (tid == 0) {
            float total = 0.0f;
            #pragma unroll
            for (int i = 0; i < 8; i++) total += sm.c.rL[i];
            out[0] = total * (1.0f / (float)B);
            g_done = 0;   // reset for next graph replay
        }
    }
}

// ---------------------------------------------------------------------------
extern "C" void kernel_launch(void* const* d_in, const int* in_sizes, int n_in,
                              void* d_out, int out_size) {
    const float* se  = (const float*)d_in[0];
    const float* c0  = (const float*)d_in[1];
    const float* c1  = (const float*)d_in[2];
    const float* c2  = (const float*)d_in[3];
    const int* i2c0  = (const int*)d_in[4];
    const int* i2c1  = (const int*)d_in[5];
    const int* i2c2  = (const int*)d_in[6];
    const int* index = (const int*)d_in[7];
    const int* neg   = (const int*)d_in[8];
    float* out = (float*)d_out;

    hirl<<<NPROD + B, 256>>>(se, c0, c1, c2, i2c0, i2c1, i2c2, index, neg, out);
}

// round 14
// speedup vs baseline: 1.1366x; 1.1366x over previous
#include <cuda_runtime.h>
#include <cuda_fp16.h>
#include <mma.h>
#include <math.h>

// Problem constants
#define B      256
#define NNEG   1000
#define H      3
#define D      128
#define CMAX   250          // neg indices < min(NUM_CLUSTER) = 250
#define CPAD   256          // padded cluster dim
#define EPSF   1e-6f
#define NPROD  192          // 4 c-tiles x 16 b-groups x 3 h
#define NGRP   16           // b-groups of 16
#define PROD_PER_GRP 12     // 4 c-tiles x 3 h

using namespace nvcuda;

// Device globals (no allocation allowed)
__device__ float g_S[B * H * CPAD];       // sim matrix (dot+1)/2, [b][h][c]
__device__ float g_loss[B];               // per-sample loss
__device__ volatile int g_cntP[NGRP];     // producer arrivals per group
__device__ int   g_cntC[NGRP];            // consumer completions per group
__device__ unsigned int g_done = 0;       // global completion counter

union SMem {
    struct {                               // producer view (~20.6 KB)
        __half A[16 * 128];                // se tile fp16 (4 KB); reused as C fp32
        __half Bt[64 * 128];               // centroid tile fp16 (16 KB)
        float  invSe[16];
        float  invC[64];
    } p;
    struct {                               // consumer view (~3.1 KB)
        float sS[H * CPAD];
        float sPos[H];
        int   sLab[H];
        float rL[8];
        float rC[8];
        int   sLast;
    } c;
};

__global__ void __launch_bounds__(256, 4)
hirl(const float* __restrict__ se,
     const float* __restrict__ c0,
     const float* __restrict__ c1,
     const float* __restrict__ c2,
     const int* __restrict__ i2c0,
     const int* __restrict__ i2c1,
     const int* __restrict__ i2c2,
     const int* __restrict__ index,
     const int* __restrict__ neg,
     float* __restrict__ out) {
    __shared__ __align__(32) SMem sm;

    const int tid  = threadIdx.x;
    const int w    = tid >> 5;
    const int lane = tid & 31;
    const int bid  = blockIdx.x;

    if (bid < NPROD) {
        // ============ PRODUCER: 16b x 64c wmma sim tile ============
        const int x = bid & 3;               // c-tile 0..3
        const int y = (bid >> 2) & 15;       // b-group 0..15 (16 b's each)
        const int h = bid >> 6;              // 0..2
        const int cbase = x * 64;
        const int b0 = y * 16;
        const float* cents = (h == 0) ? c0 : (h == 1) ? c1 : c2;

        // A: warp w loads 2 se rows (w*2, w*2+1), norms via shfl, fp16 to smem.
        #pragma unroll
        for (int rr = 0; rr < 2; rr++) {
            int row = w * 2 + rr;
            float4 v = ((const float4*)(se + ((size_t)(b0 + row) * H + h) * D))[lane];
            float ss = v.x * v.x + v.y * v.y + v.z * v.z + v.w * v.w;
            #pragma unroll
            for (int o = 16; o > 0; o >>= 1) ss += __shfl_xor_sync(0xffffffffu, ss, o);
            if (lane == 0) sm.p.invSe[row] = 1.0f / fmaxf(sqrtf(ss), 1e-12f);
            __half2* dst = (__half2*)(sm.p.A + row * 128 + lane * 4);
            dst[0] = __floats2half2_rn(v.x, v.y);
            dst[1] = __floats2half2_rn(v.z, v.w);
        }
        // B: warp w loads 8 centroid rows.
        #pragma unroll
        for (int rr = 0; rr < 8; rr++) {
            int row = w * 8 + rr;
            int c = cbase + row;
            float4 v = make_float4(0.f, 0.f, 0.f, 0.f);
            if (c < CMAX) v = ((const float4*)(cents + (size_t)c * D))[lane];
            float ss = v.x * v.x + v.y * v.y + v.z * v.z + v.w * v.w;
            #pragma unroll
            for (int o = 16; o > 0; o >>= 1) ss += __shfl_xor_sync(0xffffffffu, ss, o);
            if (lane == 0)
                sm.p.invC[row] = (c < CMAX) ? 1.0f / fmaxf(sqrtf(ss), 1e-12f) : 0.0f;
            __half2* dst = (__half2*)(sm.p.Bt + row * 128 + lane * 4);
            dst[0] = __floats2half2_rn(v.x, v.y);
            dst[1] = __floats2half2_rn(v.z, v.w);
        }
        __syncthreads();

        // wmma: warps 0-3, warp w -> c-subtile w (16 cols), full K.
        wmma::fragment<wmma::accumulator, 16, 16, 16, float> fc;
        if (w < 4) {
            wmma::fill_fragment(fc, 0.0f);
            wmma::fragment<wmma::matrix_a, 16, 16, 16, __half, wmma::row_major> fa;
            wmma::fragment<wmma::matrix_b, 16, 16, 16, __half, wmma::col_major> fb;
            #pragma unroll
            for (int k = 0; k < 8; k++) {
                wmma::load_matrix_sync(fa, sm.p.A + k * 16, 128);
                wmma::load_matrix_sync(fb, sm.p.Bt + (w * 16) * 128 + k * 16, 128);
                wmma::mma_sync(fc, fa, fb, fc);
            }
        }
        __syncthreads();     // ALL warps: everyone done reading A before reuse

        if (w < 4) {
            // C tile into reused A space (16x64 fp32 = 4 KB).
            wmma::store_matrix_sync(((float*)sm.p.A) + w * 16, fc, 64,
                                    wmma::mem_row_major);
        }
        __syncthreads();

        // Scale + write g_S: 256 float4 chunks, 1 per thread.
        {
            const float* C_s = (const float*)sm.p.A;
            int bi = tid >> 4;               // 0..15
            int ci = (tid & 15) * 4;         // 0..60
            float4 v = ((const float4*)C_s)[tid];
            float is = sm.p.invSe[bi];
            v.x = (v.x * is * sm.p.invC[ci + 0] + 1.0f) * 0.5f;
            v.y = (v.y * is * sm.p.invC[ci + 1] + 1.0f) * 0.5f;
            v.z = (v.z * is * sm.p.invC[ci + 2] + 1.0f) * 0.5f;
            v.w = (v.w * is * sm.p.invC[ci + 3] + 1.0f) * 0.5f;
            *((float4*)(g_S + ((size_t)(b0 + bi) * H + h) * CPAD + cbase + ci)) = v;
        }
        __syncthreads();
        if (tid == 0) {
            __threadfence();                 // release g_S stores
            atomicAdd((int*)&g_cntP[y], 1);
        }
        return;
    }

    // ============ CONSUMER: loss for one b ============
    const int b = bid - NPROD;
    const int grp = b >> 4;

    // ---- pre-wait #1: neg triples into registers (4 per thread) ----
    int4 na, nb, nc;
    const bool on = (tid < 250);
    if (on) {
        const int4* p = ((const int4*)(neg + (size_t)b * NNEG * H)) + tid * 3;
        na = p[0]; nb = p[1]; nc = p[2];
    }

    // ---- pre-wait #2: pos path (warps 0-2, h = w) ----
    if (w < H) {
        int idx = index[b];
        const int*   i2c   = (w == 0) ? i2c0 : (w == 1) ? i2c1 : i2c2;
        const float* cents = (w == 0) ? c0   : (w == 1) ? c1   : c2;
        int lab = i2c[idx];
        float4 cv = ((const float4*)(cents + (size_t)lab * D))[lane];
        float4 sv = ((const float4*)(se + ((size_t)b * H + w) * D))[lane];
        float cc = cv.x * cv.x + cv.y * cv.y + cv.z * cv.z + cv.w * cv.w;
        float ee = sv.x * sv.x + sv.y * sv.y + sv.z * sv.z + sv.w * sv.w;
        float dd = cv.x * sv.x + cv.y * sv.y + cv.z * sv.z + cv.w * sv.w;
        #pragma unroll
        for (int o = 16; o > 0; o >>= 1) {
            cc += __shfl_xor_sync(0xffffffffu, cc, o);
            ee += __shfl_xor_sync(0xffffffffu, ee, o);
            dd += __shfl_xor_sync(0xffffffffu, dd, o);
        }
        if (lane == 0) {
            float s = dd / (fmaxf(sqrtf(cc), 1e-12f) * fmaxf(sqrtf(ee), 1e-12f));
            sm.c.sPos[w] = (s + 1.0f) * 0.5f;
            sm.c.sLab[w] = lab;
        }
    }

    // ---- wait: plain volatile L2 reads (no atomic contention) ----
    if (tid == 0) {
        while (g_cntP[grp] < PROD_PER_GRP) __nanosleep(256);
        __threadfence();                     // acquire
    }
    __syncthreads();

    // ---- stage S row (3 KB) ----
    if (tid < 192)
        ((float4*)sm.c.sS)[tid] = ((const float4*)(g_S + (size_t)b * H * CPAD))[tid];
    __syncthreads();

    // ---- loss: 4 negs/thread, ONE log per thread (merged product) ----
    const int lab0 = sm.c.sLab[0], lab1 = sm.c.sLab[1], lab2 = sm.c.sLab[2];
    float prodv = 1.0f, cnt = 0.0f;
    if (on) {
        int idx0[4] = { na.x, na.w, nb.z, nc.y };
        int idx1[4] = { na.y, nb.x, nb.w, nc.z };
        int idx2[4] = { na.z, nb.y, nc.x, nc.w };
        #pragma unroll
        for (int k = 0; k < 4; k++) {
            int i0 = idx0[k], i1 = idx1[k], i2 = idx2[k];
            float p = sm.c.sS[i0] * sm.c.sS[CPAD + i1] * sm.c.sS[2 * CPAD + i2];
            bool tn = (i0 != lab0) || (i1 != lab1) || (i2 != lab2);
            if (tn) {
                prodv *= (1.0f - p + EPSF);
                cnt   += 1.0f;
            }
        }
    }
    float sumL = -__logf(prodv);
    #pragma unroll
    for (int o = 16; o > 0; o >>= 1) {
        sumL += __shfl_xor_sync(0xffffffffu, sumL, o);
        cnt  += __shfl_xor_sync(0xffffffffu, cnt,  o);
    }
    if (lane == 0) { sm.c.rL[w] = sumL; sm.c.rC[w] = cnt; }
    __syncthreads();

    if (tid == 0) {
        float sL = 0.0f, sC = 0.0f;
        #pragma unroll
        for (int i = 0; i < 8; i++) { sL += sm.c.rL[i]; sC += sm.c.rC[i]; }
        float negl = sL / (sC + EPSF);
        float posl = -__logf(sm.c.sPos[0] * sm.c.sPos[1] * sm.c.sPos[2] + EPSF);
        g_loss[b] = 0.5f * (posl + negl);
        __threadfence();
        // group bookkeeping: 16th consumer resets this group's counters
        int cc2 = atomicAdd(&g_cntC[grp], 1);
        if (cc2 == 15) {
            *((int*)&g_cntP[grp]) = 0;
            g_cntC[grp] = 0;
        }
        unsigned int t = atomicAdd(&g_done, 1u);
        sm.c.sLast = (t == (unsigned)(B - 1)) ? 1 : 0;
    }
    __syncthreads();

    // ---- last consumer: deterministic final mean ----
    if (sm.c.sLast) {
        __threadfence();
        float v = *((volatile float*)&g_loss[tid]);   // tid 0..255 == b
        #pragma unroll
        for (int o = 16; o > 0; o >>= 1) v += __shfl_xor_sync(0xffffffffu, v, o);
        if (lane == 0) sm.c.rL[w] = v;
        __syncthreads();
        if (tid == 0) {
            float total = 0.0f;
            #pragma unroll
            for (int i = 0; i < 8; i++) total += sm.c.rL[i];
            out[0] = total * (1.0f / (float)B);
            g_done = 0;   // reset for next graph replay
        }
    }
}

// ---------------------------------------------------------------------------
extern "C" void kernel_launch(void* const* d_in, const int* in_sizes, int n_in,
                              void* d_out, int out_size) {
    const float* se  = (const float*)d_in[0];
    const float* c0  = (const float*)d_in[1];
    const float* c1  = (const float*)d_in[2];
    const float* c2  = (const float*)d_in[3];
    const int* i2c0  = (const int*)d_in[4];
    const int* i2c1  = (const int*)d_in[5];
    const int* i2c2  = (const int*)d_in[6];
    const int* index = (const int*)d_in[7];
    const int* neg   = (const int*)d_in[8];
    float* out = (float*)d_out;

    hirl<<<NPROD + B, 256>>>(se, c0, c1, c2, i2c0, i2c1, i2c2, index, neg, out);
}

// round 15
// speedup vs baseline: 1.2691x; 1.1165x over previous
#include <cuda_runtime.h>
#include <cuda_fp16.h>
#include <mma.h>
#include <math.h>

// Problem constants
#define B      256
#define NNEG   1000
#define H      3
#define D      128
#define CMAX   250          // neg indices < min(NUM_CLUSTER) = 250
#define CPAD   256          // padded cluster dim
#define EPSF   1e-6f
#define NPROD  192          // 4 c-tiles x 16 b-groups x 3 h
#define NGRP   16           // b-groups of 16
#define PROD_PER_GRP 12     // 4 c-tiles x 3 h

using namespace nvcuda;

// Device globals (no allocation allowed)
__device__ float g_S[B * H * CPAD];       // sim matrix (dot+1)/2, [b][h][c]
__device__ float g_loss[B];               // per-sample loss
__device__ volatile int g_cntP[NGRP];     // producer arrivals per group
__device__ int   g_cntC[NGRP];            // consumer completions per group
__device__ unsigned int g_done = 0;       // global completion counter

union SMem {
    struct {                               // producer view (~20.6 KB)
        __half A[16 * 128];                // se tile fp16 (4 KB); reused as C fp32
        __half Bt[64 * 128];               // centroid tile fp16 (16 KB)
        float  invSe[16];
        float  invC[64];
    } p;
    struct {                               // consumer view (~3.1 KB)
        float sS[H * CPAD];
        float sPos[H];
        int   sLab[H];
        float rL[8];
        float rC[8];
        int   sLast;
    } c;
};

__global__ void __launch_bounds__(256, 4)
hirl(const float* __restrict__ se,
     const float* __restrict__ c0,
     const float* __restrict__ c1,
     const float* __restrict__ c2,
     const int* __restrict__ i2c0,
     const int* __restrict__ i2c1,
     const int* __restrict__ i2c2,
     const int* __restrict__ index,
     const int* __restrict__ neg,
     float* __restrict__ out) {
    __shared__ __align__(32) SMem sm;

    const int tid  = threadIdx.x;
    const int w    = tid >> 5;
    const int lane = tid & 31;
    const int bid  = blockIdx.x;

    if (bid < NPROD) {
        // ============ PRODUCER: 16b x 64c wmma sim tile ============
        const int x = bid & 3;               // c-tile 0..3
        const int y = (bid >> 2) & 15;       // b-group 0..15 (16 b's each)
        const int h = bid >> 6;              // 0..2
        const int cbase = x * 64;
        const int b0 = y * 16;
        const float* cents = (h == 0) ? c0 : (h == 1) ? c1 : c2;

        // A: warp w loads its 2 se rows BATCHED (MLP=2), then interleaved reduce.
        {
            float4 vA[2];
            #pragma unroll
            for (int rr = 0; rr < 2; rr++)
                vA[rr] = ((const float4*)(se + ((size_t)(b0 + w * 2 + rr) * H + h) * D))[lane];
            float ssA[2];
            #pragma unroll
            for (int rr = 0; rr < 2; rr++) {
                float4 v = vA[rr];
                ssA[rr] = v.x * v.x + v.y * v.y + v.z * v.z + v.w * v.w;
                __half2* dst = (__half2*)(sm.p.A + (w * 2 + rr) * 128 + lane * 4);
                dst[0] = __floats2half2_rn(v.x, v.y);
                dst[1] = __floats2half2_rn(v.z, v.w);
            }
            #pragma unroll
            for (int o = 16; o > 0; o >>= 1) {
                ssA[0] += __shfl_xor_sync(0xffffffffu, ssA[0], o);
                ssA[1] += __shfl_xor_sync(0xffffffffu, ssA[1], o);
            }
            if (lane == 0) {
                sm.p.invSe[w * 2 + 0] = 1.0f / fmaxf(sqrtf(ssA[0]), 1e-12f);
                sm.p.invSe[w * 2 + 1] = 1.0f / fmaxf(sqrtf(ssA[1]), 1e-12f);
            }
        }
        // B: warp w loads 8 centroid rows in two MLP=4 batches; interleaved reduce.
        #pragma unroll
        for (int half = 0; half < 2; half++) {
            float4 vB[4];
            #pragma unroll
            for (int rr = 0; rr < 4; rr++) {
                int c = cbase + w * 8 + half * 4 + rr;
                vB[rr] = (c < CMAX)
                    ? ((const float4*)(cents + (size_t)c * D))[lane]
                    : make_float4(0.f, 0.f, 0.f, 0.f);
            }
            float ssB[4];
            #pragma unroll
            for (int rr = 0; rr < 4; rr++) {
                float4 v = vB[rr];
                ssB[rr] = v.x * v.x + v.y * v.y + v.z * v.z + v.w * v.w;
                int row = w * 8 + half * 4 + rr;
                __half2* dst = (__half2*)(sm.p.Bt + row * 128 + lane * 4);
                dst[0] = __floats2half2_rn(v.x, v.y);
                dst[1] = __floats2half2_rn(v.z, v.w);
            }
            #pragma unroll
            for (int o = 16; o > 0; o >>= 1) {
                #pragma unroll
                for (int rr = 0; rr < 4; rr++)
                    ssB[rr] += __shfl_xor_sync(0xffffffffu, ssB[rr], o);
            }
            if (lane == 0) {
                #pragma unroll
                for (int rr = 0; rr < 4; rr++) {
                    int row = w * 8 + half * 4 + rr;
                    sm.p.invC[row] = (cbase + row < CMAX)
                        ? 1.0f / fmaxf(sqrtf(ssB[rr]), 1e-12f) : 0.0f;
                }
            }
        }
        __syncthreads();

        // wmma: warps 0-3, warp w -> c-subtile w (16 cols), full K.
        wmma::fragment<wmma::accumulator, 16, 16, 16, float> fc;
        if (w < 4) {
            wmma::fill_fragment(fc, 0.0f);
            wmma::fragment<wmma::matrix_a, 16, 16, 16, __half, wmma::row_major> fa;
            wmma::fragment<wmma::matrix_b, 16, 16, 16, __half, wmma::col_major> fb;
            #pragma unroll
            for (int k = 0; k < 8; k++) {
                wmma::load_matrix_sync(fa, sm.p.A + k * 16, 128);
                wmma::load_matrix_sync(fb, sm.p.Bt + (w * 16) * 128 + k * 16, 128);
                wmma::mma_sync(fc, fa, fb, fc);
            }
        }
        __syncthreads();     // ALL warps: everyone done reading A before reuse

        if (w < 4) {
            wmma::store_matrix_sync(((float*)sm.p.A) + w * 16, fc, 64,
                                    wmma::mem_row_major);
        }
        __syncthreads();

        // Scale + write g_S: 256 float4 chunks, 1 per thread.
        {
            const float* C_s = (const float*)sm.p.A;
            int bi = tid >> 4;               // 0..15
            int ci = (tid & 15) * 4;         // 0..60
            float4 v = ((const float4*)C_s)[tid];
            float is = sm.p.invSe[bi];
            v.x = (v.x * is * sm.p.invC[ci + 0] + 1.0f) * 0.5f;
            v.y = (v.y * is * sm.p.invC[ci + 1] + 1.0f) * 0.5f;
            v.z = (v.z * is * sm.p.invC[ci + 2] + 1.0f) * 0.5f;
            v.w = (v.w * is * sm.p.invC[ci + 3] + 1.0f) * 0.5f;
            *((float4*)(g_S + ((size_t)(b0 + bi) * H + h) * CPAD + cbase + ci)) = v;
        }
        __syncthreads();
        if (tid == 0) {
            __threadfence();                 // release g_S stores
            atomicAdd((int*)&g_cntP[y], 1);
        }
        return;
    }

    // ============ CONSUMER: loss for one b ============
    const int b = bid - NPROD;
    const int grp = b >> 4;

    // ---- pre-wait #1: neg triples into registers (4 per thread) ----
    int4 na, nb, nc;
    const bool on = (tid < 250);
    if (on) {
        const int4* p = ((const int4*)(neg + (size_t)b * NNEG * H)) + tid * 3;
        na = p[0]; nb = p[1]; nc = p[2];
    }

    // ---- pre-wait #2: pos path (warps 0-2, h = w) ----
    if (w < H) {
        int idx = index[b];
        const int*   i2c   = (w == 0) ? i2c0 : (w == 1) ? i2c1 : i2c2;
        const float* cents = (w == 0) ? c0   : (w == 1) ? c1   : c2;
        int lab = i2c[idx];
        float4 cv = ((const float4*)(cents + (size_t)lab * D))[lane];
        float4 sv = ((const float4*)(se + ((size_t)b * H + w) * D))[lane];
        float cc = cv.x * cv.x + cv.y * cv.y + cv.z * cv.z + cv.w * cv.w;
        float ee = sv.x * sv.x + sv.y * sv.y + sv.z * sv.z + sv.w * sv.w;
        float dd = cv.x * sv.x + cv.y * sv.y + cv.z * sv.z + cv.w * sv.w;
        #pragma unroll
        for (int o = 16; o > 0; o >>= 1) {
            cc += __shfl_xor_sync(0xffffffffu, cc, o);
            ee += __shfl_xor_sync(0xffffffffu, ee, o);
            dd += __shfl_xor_sync(0xffffffffu, dd, o);
        }
        if (lane == 0) {
            float s = dd / (fmaxf(sqrtf(cc), 1e-12f) * fmaxf(sqrtf(ee), 1e-12f));
            sm.c.sPos[w] = (s + 1.0f) * 0.5f;
            sm.c.sLab[w] = lab;
        }
    }

    // ---- wait: plain volatile L2 reads, tight wakeup ----
    if (tid == 0) {
        while (g_cntP[grp] < PROD_PER_GRP) __nanosleep(64);
        __threadfence();                     // acquire
    }
    __syncthreads();

    // ---- stage S row (3 KB) ----
    if (tid < 192)
        ((float4*)sm.c.sS)[tid] = ((const float4*)(g_S + (size_t)b * H * CPAD))[tid];
    __syncthreads();

    // ---- loss: 4 negs/thread, ONE log per thread (merged product) ----
    const int lab0 = sm.c.sLab[0], lab1 = sm.c.sLab[1], lab2 = sm.c.sLab[2];
    float prodv = 1.0f, cnt = 0.0f;
    if (on) {
        int idx0[4] = { na.x, na.w, nb.z, nc.y };
        int idx1[4] = { na.y, nb.x, nb.w, nc.z };
        int idx2[4] = { na.z, nb.y, nc.x, nc.w };
        #pragma unroll
        for (int k = 0; k < 4; k++) {
            int i0 = idx0[k], i1 = idx1[k], i2 = idx2[k];
            float p = sm.c.sS[i0] * sm.c.sS[CPAD + i1] * sm.c.sS[2 * CPAD + i2];
            bool tn = (i0 != lab0) || (i1 != lab1) || (i2 != lab2);
            if (tn) {
                prodv *= (1.0f - p + EPSF);
                cnt   += 1.0f;
            }
        }
    }
    float sumL = -__logf(prodv);
    #pragma unroll
    for (int o = 16; o > 0; o >>= 1) {
        sumL += __shfl_xor_sync(0xffffffffu, sumL, o);
        cnt  += __shfl_xor_sync(0xffffffffu, cnt,  o);
    }
    if (lane == 0) { sm.c.rL[w] = sumL; sm.c.rC[w] = cnt; }
    __syncthreads();

    if (tid == 0) {
        float sL = 0.0f, sC = 0.0f;
        #pragma unroll
        for (int i = 0; i < 8; i++) { sL += sm.c.rL[i]; sC += sm.c.rC[i]; }
        float negl = sL / (sC + EPSF);
        float posl = -__logf(sm.c.sPos[0] * sm.c.sPos[1] * sm.c.sPos[2] + EPSF);
        g_loss[b] = 0.5f * (posl + negl);
        __threadfence();
        // group bookkeeping: 16th consumer resets this group's counters
        int cc2 = atomicAdd(&g_cntC[grp], 1);
        if (cc2 == 15) {
            *((int*)&g_cntP[grp]) = 0;
            g_cntC[grp] = 0;
        }
        unsigned int t = atomicAdd(&g_done, 1u);
        sm.c.sLast = (t == (unsigned)(B - 1)) ? 1 : 0;
    }
    __syncthreads();

    // ---- last consumer: deterministic final mean ----
    if (sm.c.sLast) {
        __threadfence();
        float v = *((volatile float*)&g_loss[tid]);   // tid 0..255 == b
        #pragma unroll
        for (int o = 16; o > 0; o >>= 1) v += __shfl_xor_sync(0xffffffffu, v, o);
        if (lane == 0) sm.c.rL[w] = v;
        __syncthreads();
        if (tid == 0) {
            float total = 0.0f;
            #pragma unroll
            for (int i = 0; i < 8; i++) total += sm.c.rL[i];
            out[0] = total * (1.0f / (float)B);
            g_done = 0;   // reset for next graph replay
        }
    }
}

// ---------------------------------------------------------------------------
extern "C" void kernel_launch(void* const* d_in, const int* in_sizes, int n_in,
                              void* d_out, int out_size) {
    const float* se  = (const float*)d_in[0];
    const float* c0  = (const float*)d_in[1];
    const float* c1  = (const float*)d_in[2];
    const float* c2  = (const float*)d_in[3];
    const int* i2c0  = (const int*)d_in[4];
    const int* i2c1  = (const int*)d_in[5];
    const int* i2c2  = (const int*)d_in[6];
    const int* index = (const int*)d_in[7];
    const int* neg   = (const int*)d_in[8];
    float* out = (float*)d_out;

    hirl<<<NPROD + B, 256>>>(se, c0, c1, c2, i2c0, i2c1, i2c2, index, neg, out);
}

// round 16
// speedup vs baseline: 1.2909x; 1.0172x over previous
#include <cuda_runtime.h>
#include <cuda_fp16.h>
#include <mma.h>
#include <math.h>

// Problem constants
#define B      256
#define NNEG   1000
#define H      3
#define D      128
#define CMAX   250          // neg indices < min(NUM_CLUSTER) = 250
#define CPAD   256          // padded cluster dim
#define EPSF   1e-6f
#define NPROD  192          // 4 c-tiles x 16 b-groups x 3 h
#define NGRP   16           // b-groups of 16
#define PROD_PER_GRP 12     // 4 c-tiles x 3 h

using namespace nvcuda;

// Device globals (no allocation allowed)
__device__ float g_S[B * H * CPAD];       // sim matrix (dot+1)/2, [b][h][c]
__device__ float g_loss[B];               // per-sample loss
__device__ volatile int g_cntP[NGRP];     // producer arrivals per group
__device__ int   g_cntC[NGRP];            // consumer completions per group
__device__ unsigned int g_done = 0;       // global completion counter

union SMem {
    struct {                               // producer view (~24.6 KB)
        __half A[16 * 128];                // se tile fp16 (4 KB)
        __half Bt[64 * 128];               // centroid tile fp16 (16 KB)
        float  C[16 * 64];                 // fp32 C tile (4 KB, own region)
        float  invSe[16];
        float  invC[64];
    } p;
    struct {                               // consumer view (~3.1 KB)
        float sS[H * CPAD];
        float sPos[H];
        int   sLab[H];
        float rL[8];
        float rC[8];
        int   sLast;
    } c;
};

__global__ void __launch_bounds__(256, 4)
hirl(const float* __restrict__ se,
     const float* __restrict__ c0,
     const float* __restrict__ c1,
     const float* __restrict__ c2,
     const int* __restrict__ i2c0,
     const int* __restrict__ i2c1,
     const int* __restrict__ i2c2,
     const int* __restrict__ index,
     const int* __restrict__ neg,
     float* __restrict__ out) {
    __shared__ __align__(32) SMem sm;

    const int tid  = threadIdx.x;
    const int w    = tid >> 5;
    const int lane = tid & 31;
    const int bid  = blockIdx.x;

    if (bid < NPROD) {
        // ============ PRODUCER: 16b x 64c wmma sim tile ============
        const int x = bid & 3;               // c-tile 0..3
        const int y = (bid >> 2) & 15;       // b-group 0..15 (16 b's each)
        const int h = bid >> 6;              // 0..2
        const int cbase = x * 64;
        const int b0 = y * 16;
        const float* cents = (h == 0) ? c0 : (h == 1) ? c1 : c2;

        // A: warp w loads its 2 se rows BATCHED (MLP=2), interleaved reduce.
        {
            float4 vA[2];
            #pragma unroll
            for (int rr = 0; rr < 2; rr++)
                vA[rr] = ((const float4*)(se + ((size_t)(b0 + w * 2 + rr) * H + h) * D))[lane];
            float ssA[2];
            #pragma unroll
            for (int rr = 0; rr < 2; rr++) {
                float4 v = vA[rr];
                ssA[rr] = v.x * v.x + v.y * v.y + v.z * v.z + v.w * v.w;
                __half2* dst = (__half2*)(sm.p.A + (w * 2 + rr) * 128 + lane * 4);
                dst[0] = __floats2half2_rn(v.x, v.y);
                dst[1] = __floats2half2_rn(v.z, v.w);
            }
            #pragma unroll
            for (int o = 16; o > 0; o >>= 1) {
                ssA[0] += __shfl_xor_sync(0xffffffffu, ssA[0], o);
                ssA[1] += __shfl_xor_sync(0xffffffffu, ssA[1], o);
            }
            if (lane == 0) {
                sm.p.invSe[w * 2 + 0] = 1.0f / fmaxf(sqrtf(ssA[0]), 1e-12f);
                sm.p.invSe[w * 2 + 1] = 1.0f / fmaxf(sqrtf(ssA[1]), 1e-12f);
            }
        }
        // B: warp w loads 8 centroid rows in two MLP=4 batches; interleaved reduce.
        #pragma unroll
        for (int half = 0; half < 2; half++) {
            float4 vB[4];
            #pragma unroll
            for (int rr = 0; rr < 4; rr++) {
                int c = cbase + w * 8 + half * 4 + rr;
                vB[rr] = (c < CMAX)
                    ? ((const float4*)(cents + (size_t)c * D))[lane]
                    : make_float4(0.f, 0.f, 0.f, 0.f);
            }
            float ssB[4];
            #pragma unroll
            for (int rr = 0; rr < 4; rr++) {
                float4 v = vB[rr];
                ssB[rr] = v.x * v.x + v.y * v.y + v.z * v.z + v.w * v.w;
                int row = w * 8 + half * 4 + rr;
                __half2* dst = (__half2*)(sm.p.Bt + row * 128 + lane * 4);
                dst[0] = __floats2half2_rn(v.x, v.y);
                dst[1] = __floats2half2_rn(v.z, v.w);
            }
            #pragma unroll
            for (int o = 16; o > 0; o >>= 1) {
                #pragma unroll
                for (int rr = 0; rr < 4; rr++)
                    ssB[rr] += __shfl_xor_sync(0xffffffffu, ssB[rr], o);
            }
            if (lane == 0) {
                #pragma unroll
                for (int rr = 0; rr < 4; rr++) {
                    int row = w * 8 + half * 4 + rr;
                    sm.p.invC[row] = (cbase + row < CMAX)
                        ? 1.0f / fmaxf(sqrtf(ssB[rr]), 1e-12f) : 0.0f;
                }
            }
        }
        __syncthreads();     // A/Bt/invSe/invC ready

        // wmma warps 0-3: mma -> own C region -> scale -> write g_S.
        if (w < 4) {
            wmma::fragment<wmma::accumulator, 16, 16, 16, float> fc;
            wmma::fill_fragment(fc, 0.0f);
            wmma::fragment<wmma::matrix_a, 16, 16, 16, __half, wmma::row_major> fa;
            wmma::fragment<wmma::matrix_b, 16, 16, 16, __half, wmma::col_major> fb;
            #pragma unroll
            for (int k = 0; k < 8; k++) {
                wmma::load_matrix_sync(fa, sm.p.A + k * 16, 128);
                wmma::load_matrix_sync(fb, sm.p.Bt + (w * 16) * 128 + k * 16, 128);
                wmma::mma_sync(fc, fa, fb, fc);
            }
            // C region is separate smem: no cross-warp hazard, no block barrier.
            wmma::store_matrix_sync(sm.p.C + w * 16, fc, 64, wmma::mem_row_major);
            __syncwarp();    // order own store -> own loads

            // Scale + write own 16x16 sub-tile: 64 float4 chunks, 2 per lane.
            #pragma unroll
            for (int j = 0; j < 2; j++) {
                int chunk = lane * 2 + j;          // 0..63
                int row = chunk >> 2;              // 0..15
                int c4 = (chunk & 3) * 4;          // 0,4,8,12
                float4 v = *((const float4*)(sm.p.C + row * 64 + w * 16 + c4));
                float is = sm.p.invSe[row];
                v.x = (v.x * is * sm.p.invC[w * 16 + c4 + 0] + 1.0f) * 0.5f;
                v.y = (v.y * is * sm.p.invC[w * 16 + c4 + 1] + 1.0f) * 0.5f;
                v.z = (v.z * is * sm.p.invC[w * 16 + c4 + 2] + 1.0f) * 0.5f;
                v.w = (v.w * is * sm.p.invC[w * 16 + c4 + 3] + 1.0f) * 0.5f;
                *((float4*)(g_S + ((size_t)(b0 + row) * H + h) * CPAD
                            + cbase + w * 16 + c4)) = v;
            }
        }
        __syncthreads();     // all g_S writes done before release
        if (tid == 0) {
            __threadfence();                 // release g_S stores
            atomicAdd((int*)&g_cntP[y], 1);
        }
        return;
    }

    // ============ CONSUMER: loss for one b ============
    const int b = bid - NPROD;
    const int grp = b >> 4;

    // ---- pre-wait #1: neg triples into registers (4 per thread) ----
    int4 na, nb, nc;
    const bool on = (tid < 250);
    if (on) {
        const int4* p = ((const int4*)(neg + (size_t)b * NNEG * H)) + tid * 3;
        na = p[0]; nb = p[1]; nc = p[2];
    }

    // ---- pre-wait #2: pos path (warps 0-2, h = w) ----
    if (w < H) {
        int idx = index[b];
        const int*   i2c   = (w == 0) ? i2c0 : (w == 1) ? i2c1 : i2c2;
        const float* cents = (w == 0) ? c0   : (w == 1) ? c1   : c2;
        int lab = i2c[idx];
        float4 cv = ((const float4*)(cents + (size_t)lab * D))[lane];
        float4 sv = ((const float4*)(se + ((size_t)b * H + w) * D))[lane];
        float cc = cv.x * cv.x + cv.y * cv.y + cv.z * cv.z + cv.w * cv.w;
        float ee = sv.x * sv.x + sv.y * sv.y + sv.z * sv.z + sv.w * sv.w;
        float dd = cv.x * sv.x + cv.y * sv.y + cv.z * sv.z + cv.w * sv.w;
        #pragma unroll
        for (int o = 16; o > 0; o >>= 1) {
            cc += __shfl_xor_sync(0xffffffffu, cc, o);
            ee += __shfl_xor_sync(0xffffffffu, ee, o);
            dd += __shfl_xor_sync(0xffffffffu, dd, o);
        }
        if (lane == 0) {
            float s = dd / (fmaxf(sqrtf(cc), 1e-12f) * fmaxf(sqrtf(ee), 1e-12f));
            sm.c.sPos[w] = (s + 1.0f) * 0.5f;
            sm.c.sLab[w] = lab;
        }
    }

    // ---- wait: plain volatile L2 reads, tight wakeup ----
    if (tid == 0) {
        while (g_cntP[grp] < PROD_PER_GRP) __nanosleep(64);
        __threadfence();                     // acquire
    }
    __syncthreads();

    // ---- stage S row (3 KB) ----
    if (tid < 192)
        ((float4*)sm.c.sS)[tid] = ((const float4*)(g_S + (size_t)b * H * CPAD))[tid];
    __syncthreads();

    // ---- loss: 4 negs/thread, ONE log per thread (merged product) ----
    const int lab0 = sm.c.sLab[0], lab1 = sm.c.sLab[1], lab2 = sm.c.sLab[2];
    float prodv = 1.0f, cnt = 0.0f;
    if (on) {
        int idx0[4] = { na.x, na.w, nb.z, nc.y };
        int idx1[4] = { na.y, nb.x, nb.w, nc.z };
        int idx2[4] = { na.z, nb.y, nc.x, nc.w };
        #pragma unroll
        for (int k = 0; k < 4; k++) {
            int i0 = idx0[k], i1 = idx1[k], i2 = idx2[k];
            float p = sm.c.sS[i0] * sm.c.sS[CPAD + i1] * sm.c.sS[2 * CPAD + i2];
            bool tn = (i0 != lab0) || (i1 != lab1) || (i2 != lab2);
            if (tn) {
                prodv *= (1.0f - p + EPSF);
                cnt   += 1.0f;
            }
        }
    }
    float sumL = -__logf(prodv);
    #pragma unroll
    for (int o = 16; o > 0; o >>= 1) {
        sumL += __shfl_xor_sync(0xffffffffu, sumL, o);
        cnt  += __shfl_xor_sync(0xffffffffu, cnt,  o);
    }
    if (lane == 0) { sm.c.rL[w] = sumL; sm.c.rC[w] = cnt; }
    __syncthreads();

    if (tid == 0) {
        float sL = 0.0f, sC = 0.0f;
        #pragma unroll
        for (int i = 0; i < 8; i++) { sL += sm.c.rL[i]; sC += sm.c.rC[i]; }
        float negl = sL / (sC + EPSF);
        float posl = -__logf(sm.c.sPos[0] * sm.c.sPos[1] * sm.c.sPos[2] + EPSF);
        g_loss[b] = 0.5f * (posl + negl);
        __threadfence();
        // group bookkeeping: 16th consumer resets this group's counters
        int cc2 = atomicAdd(&g_cntC[grp], 1);
        if (cc2 == 15) {
            *((int*)&g_cntP[grp]) = 0;
            g_cntC[grp] = 0;
        }
        unsigned int t = atomicAdd(&g_done, 1u);
        sm.c.sLast = (t == (unsigned)(B - 1)) ? 1 : 0;
    }
    __syncthreads();

    // ---- last consumer: deterministic final mean ----
    if (sm.c.sLast) {
        __threadfence();
        float v = *((volatile float*)&g_loss[tid]);   // tid 0..255 == b
        #pragma unroll
        for (int o = 16; o > 0; o >>= 1) v += __shfl_xor_sync(0xffffffffu, v, o);
        if (lane == 0) sm.c.rL[w] = v;
        __syncthreads();
        if (tid == 0) {
            float total = 0.0f;
            #pragma unroll
            for (int i = 0; i < 8; i++) total += sm.c.rL[i];
            out[0] = total * (1.0f / (float)B);
            g_done = 0;   // reset for next graph replay
        }
    }
}

// ---------------------------------------------------------------------------
extern "C" void kernel_launch(void* const* d_in, const int* in_sizes, int n_in,
                              void* d_out, int out_size) {
    const float* se  = (const float*)d_in[0];
    const float* c0  = (const float*)d_in[1];
    const float* c1  = (const float*)d_in[2];
    const float* c2  = (const float*)d_in[3];
    const int* i2c0  = (const int*)d_in[4];
    const int* i2c1  = (const int*)d_in[5];
    const int* i2c2  = (const int*)d_in[6];
    const int* index = (const int*)d_in[7];
    const int* neg   = (const int*)d_in[8];
    float* out = (float*)d_out;

    hirl<<<NPROD + B, 256>>>(se, c0, c1, c2, i2c0, i2c1, i2c2, index, neg, out);
}